// round 10
// baseline (speedup 1.0000x reference)
#include <cuda_runtime.h>
#include <math.h>

// Problem constants
#define B 32
#define S 2048
#define D 1024
#define MASK_PENALTY 100000000.0f

// Tiling
#define NSPLIT 16
#define WARPS 4
#define THREADS (WARPS * 32)                    // 128
#define ROWS_PER_SPLIT (S / NSPLIT)             // 128 == THREADS

// Scratch (allocation-free: __device__ globals, zero-init)
__device__ float g_m[B * NSPLIT];
__device__ float g_l[B * NSPLIT];
__device__ __align__(16) float g_acc[(size_t)B * NSPLIT * D];  // 2 MB
__device__ int g_cnt[B];  // zero-init; self-resets each launch

// ---------------------------------------------------------------------------
// Fused single-pass online-softmax attention: mask skipping + compaction +
// EXPLICIT SOFTWARE PIPELINE (two-row register double buffer).
// Masked rows contribute exp(-1e8)==0.0f exactly in fp32 -> skipped.
// The CTA compacts valid row indices into smem (deterministic ballot/popc);
// each warp then walks its list entries with a ping-pong buffer: the next
// row's 8x LDG.128 are issued BEFORE the current row's reduce/exp/update,
// so every warp keeps ~4KB in flight through its serial compute window.
// 4 warp partials merge in smem -> 1 per CTA -> last CTA per batch merges.
// ---------------------------------------------------------------------------
__global__ void __launch_bounds__(THREADS, 3)
attn_fused(const float* __restrict__ target,
           const float* __restrict__ context,
           const float* __restrict__ mask,
           float* __restrict__ out)
{
    const int b     = blockIdx.x;
    const int split = blockIdx.y;
    const int w     = threadIdx.x >> 5;
    const int lane  = threadIdx.x & 31;
    const int s0    = split * ROWS_PER_SPLIT;

    __shared__ short slist[ROWS_PER_SPLIT];   // compacted valid row indices
    __shared__ int   swcnt[WARPS];
    __shared__ int   scnt;
    __shared__ float sm_[WARPS];
    __shared__ float sl_[WARPS];
    __shared__ __align__(16) float4 sacc[WARPS][D / 4];   // 16 KB

    // ---- Deterministic compaction (all 128 threads, 1 row each) ----
    {
        const bool v = mask[(size_t)b * S + s0 + threadIdx.x] != 0.f;
        const unsigned bal = __ballot_sync(0xffffffffu, v);
        if (lane == 0) swcnt[w] = __popc(bal);
        __syncthreads();
        int off = 0;
#pragma unroll
        for (int i = 0; i < WARPS; i++) off += (i < w) ? swcnt[i] : 0;
        if (threadIdx.x == 0)
            scnt = swcnt[0] + swcnt[1] + swcnt[2] + swcnt[3];
        if (v) {
            const int pos = off + __popc(bal & ((1u << lane) - 1u));
            slist[pos] = (short)threadIdx.x;
        }
    }

    // Lane's slice of the query vector (registers)
    const float4* tg = (const float4*)(target + (size_t)b * D);
    float4 t[8];
#pragma unroll
    for (int i = 0; i < 8; i++) t[i] = tg[lane + 32 * i];

    __syncthreads();
    const int cnt = scnt;

    float4 acc[8];
#pragma unroll
    for (int i = 0; i < 8; i++) acc[i] = make_float4(0.f, 0.f, 0.f, 0.f);

    float m = -INFINITY;
    float l = 0.f;

    const float* cb = context + (size_t)b * S * D;

    // row load into a register buffer (8 x LDG.128, coalesced)
    auto loadrow = [&](float4* c, int r) {
        const float4* row = (const float4*)(cb + (size_t)(s0 + r) * D);
#pragma unroll
        for (int i = 0; i < 8; i++) c[i] = row[lane + 32 * i];
    };
    // consume one row: dot + reduce + online-softmax update
    auto process = [&](const float4* c) {
        float d0 = 0.f, d1 = 0.f;
#pragma unroll
        for (int i = 0; i < 8; i++) {
            d0 = fmaf(c[i].x, t[i].x, d0);
            d1 = fmaf(c[i].y, t[i].y, d1);
            d0 = fmaf(c[i].z, t[i].z, d0);
            d1 = fmaf(c[i].w, t[i].w, d1);
        }
        float dot = d0 + d1;
#pragma unroll
        for (int off = 16; off > 0; off >>= 1)
            dot += __shfl_xor_sync(0xffffffffu, dot, off);

        const float mnew  = fmaxf(m, dot);
        const float scale = __expf(m - mnew);     // 0 on first valid row
        const float wgt   = __expf(dot - mnew);
        l = l * scale + wgt;
#pragma unroll
        for (int i = 0; i < 8; i++) {
            acc[i].x = fmaf(acc[i].x, scale, wgt * c[i].x);
            acc[i].y = fmaf(acc[i].y, scale, wgt * c[i].y);
            acc[i].z = fmaf(acc[i].z, scale, wgt * c[i].z);
            acc[i].w = fmaf(acc[i].w, scale, wgt * c[i].w);
        }
        m = mnew;
    };

    // ---- Explicitly pipelined mainloop (ping-pong buffers cA/cB) ----
    {
        float4 cA[8], cB[8];
        int p = w;
        if (p < cnt) {
            loadrow(cA, slist[p]);
            p += WARPS;
            while (p < cnt) {
                loadrow(cB, slist[p]);  // B's loads in flight during A's compute
                p += WARPS;
                process(cA);
                if (p >= cnt) { process(cB); goto mainloop_done; }
                loadrow(cA, slist[p]);  // A's loads in flight during B's compute
                p += WARPS;
                process(cB);
            }
            process(cA);
        }
    }
mainloop_done:

    // ---- In-CTA merge of the 4 warp partials ----
    if (lane == 0) { sm_[w] = m; sl_[w] = l; }
    __syncthreads();

    float Mcta = -INFINITY;
#pragma unroll
    for (int i = 0; i < WARPS; i++) Mcta = fmaxf(Mcta, sm_[i]);

    // Guard: warp with zero valid rows has m=-inf (Mcta may also be -inf).
    const float f = (m > -INFINITY) ? __expf(m - Mcta) : 0.f;
#pragma unroll
    for (int i = 0; i < 8; i++) {
        float4 a = acc[i];
        a.x *= f; a.y *= f; a.z *= f; a.w *= f;
        sacc[w][lane + 32 * i] = a;
    }
    __syncthreads();

    // 128 threads sum across 4 warps; each thread owns 2 float4 positions
    const int pidx = b * NSPLIT + split;
#pragma unroll
    for (int h = 0; h < 2; h++) {
        const int d4 = threadIdx.x + h * THREADS;
        float4 sum = sacc[0][d4];
#pragma unroll
        for (int i = 1; i < WARPS; i++) {
            const float4 v = sacc[i][d4];
            sum.x += v.x; sum.y += v.y; sum.z += v.z; sum.w += v.w;
        }
        ((float4*)(g_acc + (size_t)pidx * D))[d4] = sum;
    }

    if (threadIdx.x == 0) {
        float L = 0.f;
#pragma unroll
        for (int i = 0; i < WARPS; i++)
            L += (sm_[i] > -INFINITY ? __expf(sm_[i] - Mcta) : 0.f) * sl_[i];
        g_m[pidx] = Mcta;   // -inf if the whole split is masked
        g_l[pidx] = L;
    }

    // ---- Last CTA per batch merges the NSPLIT partials ----
    __threadfence();
    __syncthreads();
    __shared__ int isLast;
    if (threadIdx.x == 0)
        isLast = (atomicAdd(&g_cnt[b], 1) == NSPLIT - 1);
    __syncthreads();
    if (!isLast) return;
    __threadfence();  // acquire

    float pm[NSPLIT], pl[NSPLIT];
#pragma unroll
    for (int p = 0; p < NSPLIT; p++) {
        pm[p] = __ldcg(&g_m[b * NSPLIT + p]);
        pl[p] = __ldcg(&g_l[b * NSPLIT + p]);
    }
    // M is finite: position 0 of every batch is guaranteed valid.
    float M = -INFINITY;
#pragma unroll
    for (int p = 0; p < NSPLIT; p++) M = fmaxf(M, pm[p]);
    float L = 0.f;
#pragma unroll
    for (int p = 0; p < NSPLIT; p++)
        L += (pm[p] > -INFINITY ? __expf(pm[p] - M) : 0.f) * pl[p];
    const float Linv = 1.f / L;

#pragma unroll
    for (int h = 0; h < 2; h++) {
        const int d4 = threadIdx.x + h * THREADS;
        float4 a = make_float4(0.f, 0.f, 0.f, 0.f);
#pragma unroll
        for (int p = 0; p < NSPLIT; p++) {
            const float fp = (pm[p] > -INFINITY) ? __expf(pm[p] - M) : 0.f;
            const float4 v =
                __ldcg((const float4*)(g_acc + (size_t)(b * NSPLIT + p) * D) + d4);
            a.x = fmaf(fp, v.x, a.x);
            a.y = fmaf(fp, v.y, a.y);
            a.z = fmaf(fp, v.z, a.z);
            a.w = fmaf(fp, v.w, a.w);
        }
        a.x *= Linv; a.y *= Linv; a.z *= Linv; a.w *= Linv;
        ((float4*)(out + (size_t)b * D))[d4] = a;
    }

    if (threadIdx.x == 0) atomicExch(&g_cnt[b], 0);
}

extern "C" void kernel_launch(void* const* d_in, const int* in_sizes, int n_in,
                              void* d_out, int out_size)
{
    const float* target  = (const float*)d_in[0];  // [B, D]
    const float* context = (const float*)d_in[1];  // [B, S, D]
    const float* mask    = (const float*)d_in[2];  // [B, S]
    float* out = (float*)d_out;                    // [B, D]

    dim3 grid(B, NSPLIT);
    attn_fused<<<grid, THREADS>>>(target, context, mask, out);
}

// round 11
// speedup vs baseline: 1.0662x; 1.0662x over previous
#include <cuda_runtime.h>
#include <math.h>

// Problem constants
#define B 32
#define S 2048
#define D 1024
#define MASK_PENALTY 100000000.0f

// Tiling
#define NSPLIT 16
#define WARPS 8
#define THREADS (WARPS * 32)                    // 256
#define ROWS_PER_SPLIT (S / NSPLIT)             // 128

// Prefetch distance in list entries (per warp iterations ahead)
#define PF_DIST (2 * WARPS)

// Scratch (allocation-free: __device__ globals, zero-init)
__device__ float g_m[B * NSPLIT];
__device__ float g_l[B * NSPLIT];
__device__ __align__(16) float g_acc[(size_t)B * NSPLIT * D];  // 2 MB
__device__ int g_cnt[B];  // zero-init; self-resets each launch

__device__ __forceinline__ void prefetch_l2(const void* p) {
    asm volatile("prefetch.global.L2 [%0];" :: "l"(p));
}

// ---------------------------------------------------------------------------
// Fused single-pass online-softmax attention: mask skipping + compaction +
// L2 PREFETCH STREAM.
// Masked rows contribute exp(-1e8)==0.0f exactly in fp32 -> skipped.
// The CTA compacts valid row indices into smem (deterministic ballot/popc).
// Each warp, per iteration, issues ONE prefetch.global.L2 warp-instruction
// (32 lanes x 128B = the full 4KB row) for the row two iterations ahead:
// HBM->L2 fetch is decoupled from registers and compute windows, and the
// demand LDG.128s hit L2. 8 warp partials merge in smem -> 1 per CTA ->
// last CTA per batch merges the NSPLIT split partials (no second kernel).
// ---------------------------------------------------------------------------
__global__ void __launch_bounds__(THREADS)
attn_fused(const float* __restrict__ target,
           const float* __restrict__ context,
           const float* __restrict__ mask,
           float* __restrict__ out)
{
    const int b     = blockIdx.x;
    const int split = blockIdx.y;
    const int w     = threadIdx.x >> 5;
    const int lane  = threadIdx.x & 31;
    const int s0    = split * ROWS_PER_SPLIT;

    __shared__ short slist[ROWS_PER_SPLIT];   // compacted valid row indices
    __shared__ int   swcnt[4];
    __shared__ int   scnt;
    __shared__ float sm_[WARPS];
    __shared__ float sl_[WARPS];
    __shared__ __align__(16) float4 sacc[WARPS][D / 4];   // 32 KB

    // ---- Deterministic compaction of valid rows (warps 0-3) ----
    if (threadIdx.x < ROWS_PER_SPLIT) {
        const bool v = mask[(size_t)b * S + s0 + threadIdx.x] != 0.f;
        const unsigned bal = __ballot_sync(0xffffffffu, v);
        if (lane == 0) swcnt[w] = __popc(bal);
        __syncwarp();
        __syncthreads();
        int off = 0;
#pragma unroll
        for (int i = 0; i < 4; i++) off += (i < w) ? swcnt[i] : 0;
        if (threadIdx.x == 0) scnt = swcnt[0] + swcnt[1] + swcnt[2] + swcnt[3];
        if (v) {
            const int pos = off + __popc(bal & ((1u << lane) - 1u));
            slist[pos] = (short)threadIdx.x;
        }
    } else {
        __syncthreads();   // match the barrier above
    }

    // Lane's slice of the query vector (registers) — load while compacting
    const float4* tg = (const float4*)(target + (size_t)b * D);
    float4 t[8];
#pragma unroll
    for (int i = 0; i < 8; i++) t[i] = tg[lane + 32 * i];

    __syncthreads();
    const int cnt = scnt;

    float4 acc[8];
#pragma unroll
    for (int i = 0; i < 8; i++) acc[i] = make_float4(0.f, 0.f, 0.f, 0.f);

    float m = -INFINITY;
    float l = 0.f;

    const float* cb = context + (size_t)b * S * D;

    // Prologue: prefetch this warp's first two rows into L2
#pragma unroll
    for (int k = 0; k < 2; k++) {
        const int pf = w + k * WARPS;
        if (pf < cnt)
            prefetch_l2((const char*)(cb + (size_t)(s0 + slist[pf]) * D)
                        + 128u * lane);
    }

    // ---- Balanced mainloop over compacted valid rows, with L2 prefetch ----
    for (int p = w; p < cnt; p += WARPS) {
        // Prefetch the row two warp-iterations ahead (one warp-instruction)
        const int pf = p + PF_DIST;
        if (pf < cnt)
            prefetch_l2((const char*)(cb + (size_t)(s0 + slist[pf]) * D)
                        + 128u * lane);

        const int r = slist[p];
        const float4* row = (const float4*)(cb + (size_t)(s0 + r) * D);

        float4 c[8];
#pragma unroll
        for (int i = 0; i < 8; i++) c[i] = row[lane + 32 * i];

        // dot(context_row, target) for this lane's slice (2 chains)
        float d0 = 0.f, d1 = 0.f;
#pragma unroll
        for (int i = 0; i < 8; i++) {
            d0 = fmaf(c[i].x, t[i].x, d0);
            d1 = fmaf(c[i].y, t[i].y, d1);
            d0 = fmaf(c[i].z, t[i].z, d0);
            d1 = fmaf(c[i].w, t[i].w, d1);
        }
        float dot = d0 + d1;
#pragma unroll
        for (int off = 16; off > 0; off >>= 1)
            dot += __shfl_xor_sync(0xffffffffu, dot, off);

        // valid row => mask==1 => penalty term is 0; score = dot
        const float score = dot;

        // online softmax update
        const float mnew  = fmaxf(m, score);
        const float scale = __expf(m - mnew);     // 0 on first valid row
        const float wgt   = __expf(score - mnew);
        l = l * scale + wgt;
#pragma unroll
        for (int i = 0; i < 8; i++) {
            acc[i].x = fmaf(acc[i].x, scale, wgt * c[i].x);
            acc[i].y = fmaf(acc[i].y, scale, wgt * c[i].y);
            acc[i].z = fmaf(acc[i].z, scale, wgt * c[i].z);
            acc[i].w = fmaf(acc[i].w, scale, wgt * c[i].w);
        }
        m = mnew;
    }

    // ---- In-CTA merge of the 8 warp partials ----
    if (lane == 0) { sm_[w] = m; sl_[w] = l; }
    __syncthreads();

    float Mcta = -INFINITY;
#pragma unroll
    for (int i = 0; i < WARPS; i++) Mcta = fmaxf(Mcta, sm_[i]);

    // Guard: warp with zero valid rows has m=-inf (Mcta may also be -inf).
    const float f = (m > -INFINITY) ? __expf(m - Mcta) : 0.f;
#pragma unroll
    for (int i = 0; i < 8; i++) {
        float4 a = acc[i];
        a.x *= f; a.y *= f; a.z *= f; a.w *= f;
        sacc[w][lane + 32 * i] = a;
    }
    __syncthreads();

    // 256 threads sum across the 8 warps, write CTA partial
    const int pidx = b * NSPLIT + split;
    const int d4 = threadIdx.x;
    float4 sum = sacc[0][d4];
#pragma unroll
    for (int i = 1; i < WARPS; i++) {
        const float4 v = sacc[i][d4];
        sum.x += v.x; sum.y += v.y; sum.z += v.z; sum.w += v.w;
    }
    ((float4*)(g_acc + (size_t)pidx * D))[d4] = sum;

    if (threadIdx.x == 0) {
        float L = 0.f;
#pragma unroll
        for (int i = 0; i < WARPS; i++)
            L += (sm_[i] > -INFINITY ? __expf(sm_[i] - Mcta) : 0.f) * sl_[i];
        g_m[pidx] = Mcta;   // -inf if the whole split is masked
        g_l[pidx] = L;
    }

    // ---- Last CTA per batch merges the NSPLIT partials ----
    __threadfence();
    __syncthreads();
    __shared__ int isLast;
    if (threadIdx.x == 0)
        isLast = (atomicAdd(&g_cnt[b], 1) == NSPLIT - 1);
    __syncthreads();
    if (!isLast) return;
    __threadfence();  // acquire

    float pm[NSPLIT], pl[NSPLIT];
#pragma unroll
    for (int p = 0; p < NSPLIT; p++) {
        pm[p] = __ldcg(&g_m[b * NSPLIT + p]);
        pl[p] = __ldcg(&g_l[b * NSPLIT + p]);
    }
    // M is finite: position 0 of every batch is guaranteed valid.
    float M = -INFINITY;
#pragma unroll
    for (int p = 0; p < NSPLIT; p++) M = fmaxf(M, pm[p]);
    float L = 0.f;
#pragma unroll
    for (int p = 0; p < NSPLIT; p++)
        L += (pm[p] > -INFINITY ? __expf(pm[p] - M) : 0.f) * pl[p];
    const float Linv = 1.f / L;

    float4 a = make_float4(0.f, 0.f, 0.f, 0.f);
#pragma unroll
    for (int p = 0; p < NSPLIT; p++) {
        const float fp = (pm[p] > -INFINITY) ? __expf(pm[p] - M) : 0.f;
        const float4 v =
            __ldcg((const float4*)(g_acc + (size_t)(b * NSPLIT + p) * D) + d4);
        a.x = fmaf(fp, v.x, a.x);
        a.y = fmaf(fp, v.y, a.y);
        a.z = fmaf(fp, v.z, a.z);
        a.w = fmaf(fp, v.w, a.w);
    }
    a.x *= Linv; a.y *= Linv; a.z *= Linv; a.w *= Linv;
    ((float4*)(out + (size_t)b * D))[d4] = a;

    if (threadIdx.x == 0) atomicExch(&g_cnt[b], 0);
}

extern "C" void kernel_launch(void* const* d_in, const int* in_sizes, int n_in,
                              void* d_out, int out_size)
{
    const float* target  = (const float*)d_in[0];  // [B, D]
    const float* context = (const float*)d_in[1];  // [B, S, D]
    const float* mask    = (const float*)d_in[2];  // [B, S]
    float* out = (float*)d_out;                    // [B, D]

    dim3 grid(B, NSPLIT);
    attn_fused<<<grid, THREADS>>>(target, context, mask, out);
}